// round 1
// baseline (speedup 1.0000x reference)
#include <cuda_runtime.h>
#include <cuda_bf16.h>

// Problem constants (from reference)
#define B_   64
#define T_   2048
#define D_   512
#define H_   64
#define T1   683      // conv1 output length: floor((2048+2-3)/3)+1
#define T2   228      // conv2 output length: floor((683+2-3)/3)+1
#define KDIM 1536     // 3*512 (conv1 reduction dim)
#define NCH  128      // 2*H conv1 output channels
#define KSEL 32       // top-k = B/2

// Scratch (device globals: runtime allocation is forbidden)
__device__ float g_W[KDIM * NCH];        // w1 transposed: W[k][c], k = j*512+d
__device__ float g_h[(size_t)B_ * T1 * H_];  // maxpooled conv1 output, layout [b][t][hh]
__device__ float g_est[B_];
__device__ int   g_idx[KSEL];

// ---------------------------------------------------------------------------
// K0: transpose w1 (128, 512, 3) -> W[k=j*512+d][c]
// ---------------------------------------------------------------------------
__global__ void prep_w_kernel(const float* __restrict__ w1) {
    int o = blockIdx.x * blockDim.x + threadIdx.x;
    if (o >= KDIM * NCH) return;
    int k = o >> 7;        // / 128
    int c = o & 127;
    int j = k / D_;
    int d = k % D_;
    g_W[o] = w1[c * (D_ * 3) + d * 3 + j];
}

// ---------------------------------------------------------------------------
// K1: conv1 as SGEMM + bias + pair-maxpool epilogue.
// Block tile: 128 (t) x 128 (channels), K-chunks of 16. 256 threads, 8x8 micro.
// A[t,k] = xflat[b][(3t-1)*512 + k]  (t=0, k<512 is zero padding)
// ---------------------------------------------------------------------------
#define BM 128
#define BN 128
#define BK 16

__global__ __launch_bounds__(256) void conv1_gemm_kernel(
    const float* __restrict__ x, const float* __restrict__ b1)
{
    __shared__ float As[BK][BM + 4];
    __shared__ float Bs[BK][BN];

    const int b   = blockIdx.y;
    const int m0  = blockIdx.x * BM;
    const int tid = threadIdx.x;
    const int tx  = tid & 15;      // N direction
    const int ty  = tid >> 4;      // M direction

    const float* Ab = x + (size_t)b * T_ * D_ - D_;  // window base (t=0 starts one frame early)

    float acc[8][8];
#pragma unroll
    for (int i = 0; i < 8; i++)
#pragma unroll
        for (int j = 0; j < 8; j++) acc[i][j] = 0.f;

    for (int k0 = 0; k0 < KDIM; k0 += BK) {
        // --- load A tile (128 rows x 16 k), transposed into As[k][row] ---
#pragma unroll
        for (int p = 0; p < 2; p++) {
            int row = (tid >> 2) + p * 64;
            int kq  = (tid & 3) * 4;
            int t   = m0 + row;
            float4 v = make_float4(0.f, 0.f, 0.f, 0.f);
            // zero-fill: rows past M edge, and the left zero-pad frame (t==0, k<512)
            if (t < T1 && !(t == 0 && (k0 + kq) < D_)) {
                v = *(const float4*)(Ab + (size_t)t * KDIM + k0 + kq);
            }
            As[kq + 0][row] = v.x;
            As[kq + 1][row] = v.y;
            As[kq + 2][row] = v.z;
            As[kq + 3][row] = v.w;
        }
        // --- load B tile (16 k x 128 c), coalesced ---
#pragma unroll
        for (int p = 0; p < 2; p++) {
            int e  = tid + p * 256;
            int kk = e >> 5;
            int cq = (e & 31) * 4;
            *(float4*)&Bs[kk][cq] = *(const float4*)(g_W + (size_t)(k0 + kk) * NCH + cq);
        }
        __syncthreads();

#pragma unroll
        for (int kk = 0; kk < BK; kk++) {
            float af[8], bf[8];
#pragma unroll
            for (int i = 0; i < 8; i++) af[i] = As[kk][ty * 8 + i];
#pragma unroll
            for (int j = 0; j < 8; j++) bf[j] = Bs[kk][tx * 8 + j];
#pragma unroll
            for (int i = 0; i < 8; i++)
#pragma unroll
                for (int j = 0; j < 8; j++)
                    acc[i][j] += af[i] * bf[j];
        }
        __syncthreads();
    }

    // --- epilogue: bias + maxpool over channel pairs (2hh, 2hh+1) ---
#pragma unroll
    for (int i = 0; i < 8; i++) {
        int t = m0 + ty * 8 + i;
        if (t >= T1) continue;
#pragma unroll
        for (int j = 0; j < 8; j += 2) {
            int c  = tx * 8 + j;
            float v0 = acc[i][j]     + b1[c];
            float v1 = acc[i][j + 1] + b1[c + 1];
            g_h[((size_t)b * T1 + t) * H_ + (c >> 1)] = fmaxf(v0, v1);
        }
    }
}

// ---------------------------------------------------------------------------
// K2: conv2 (64ch -> 1, K=3, stride 3, pad 1) + per-batch score reduction.
// est[b] = sum_t2 s[b,t2] / ceil(ceil(L/3)/3)
// One block per batch, thread t2 computes one score.
// ---------------------------------------------------------------------------
__global__ void conv2_est_kernel(const float* __restrict__ w2,
                                 const float* __restrict__ b2,
                                 const int* __restrict__ seq_lens)
{
    const int b   = blockIdx.x;
    const int tid = threadIdx.x;
    __shared__ float w2s[H_ * 3];
    __shared__ float red[256];

    if (tid < H_ * 3) w2s[tid] = w2[tid];
    __syncthreads();

    float s = 0.f;
    if (tid < T2) {
        s = b2[0];
#pragma unroll
        for (int kk = 0; kk < 3; kk++) {
            int tp = tid * 3 - 1 + kk;
            if (tp >= 0 && tp < T1) {
                const float* hrow = &g_h[((size_t)b * T1 + tp) * H_];
#pragma unroll 8
                for (int hh = 0; hh < H_; hh++)
                    s += w2s[hh * 3 + kk] * hrow[hh];
            }
        }
    }
    red[tid] = s;
    __syncthreads();
    for (int off = 128; off > 0; off >>= 1) {
        if (tid < off) red[tid] += red[tid + off];
        __syncthreads();
    }
    if (tid == 0) {
        int L   = seq_lens[b];
        int sl1 = (L + 2) / 3;     // ceil(L/3)
        int sl2 = (sl1 + 2) / 3;   // ceil(sl1/3)
        g_est[b] = red[0] / (float)sl2;
    }
}

// ---------------------------------------------------------------------------
// K3: top-32 selection (jax top_k tie-break: lower index wins), output indices
// naturally in ascending order, and write sel_lens tail of d_out (as float).
// Trivial sizes (64 elements) -> single thread.
// ---------------------------------------------------------------------------
__global__ void select_kernel(const int* __restrict__ seq_lens,
                              float* __restrict__ out,
                              long long lens_off, int has_lens)
{
    if (threadIdx.x != 0) return;
    int cnt = 0;
    for (int i = 0; i < B_; i++) {
        float ei = g_est[i];
        int rank = 0;
        for (int j = 0; j < B_; j++) {
            float ej = g_est[j];
            if (ej > ei || (ej == ei && j < i)) rank++;
        }
        if (rank < KSEL) {
            g_idx[cnt] = i;
            if (has_lens) out[lens_off + cnt] = (float)seq_lens[i];
            cnt++;
        }
    }
}

// ---------------------------------------------------------------------------
// K4: gather x_sel = x[idx][:, :max_time, :], float4 copy.
// ---------------------------------------------------------------------------
__global__ void gather_kernel(const float* __restrict__ x,
                              float* __restrict__ out, int max_time)
{
    const int s = blockIdx.y;
    long long n4 = (long long)max_time * (D_ / 4);
    long long i  = (long long)blockIdx.x * blockDim.x + threadIdx.x;
    if (i >= n4) return;
    int src_b = g_idx[s];
    const float4* src = (const float4*)(x + (size_t)src_b * T_ * D_);
    float4*       dst = (float4*)(out + (size_t)s * max_time * D_);
    dst[i] = src[i];
}

// ---------------------------------------------------------------------------
// Host launcher (graph-capturable: plain kernel launches only)
// Inputs (metadata order): x, seq_lens, w1, b1, w2, b2
// Output packing assumed: [x_sel flattened (f32), sel_lens (as f32)]
// max_time is recovered host-side from out_size.
// ---------------------------------------------------------------------------
extern "C" void kernel_launch(void* const* d_in, const int* in_sizes, int n_in,
                              void* d_out, int out_size)
{
    const float* x        = (const float*)d_in[0];
    const int*   seq_lens = (const int*)  d_in[1];
    const float* w1       = (const float*)d_in[2];
    const float* b1       = (const float*)d_in[3];
    const float* w2       = (const float*)d_in[4];
    const float* b2       = (const float*)d_in[5];
    float* out = (float*)d_out;

    const long long row_elems = (long long)KSEL * D_;  // 16384 per time-step across 32 rows
    int has_lens = ((long long)out_size % row_elems) != 0;
    long long mt = has_lens ? ((long long)out_size - KSEL) / row_elems
                            : (long long)out_size / row_elems;
    int max_time = (int)mt;

    prep_w_kernel<<<(KDIM * NCH + 255) / 256, 256>>>(w1);

    dim3 g1((T1 + BM - 1) / BM, B_);
    conv1_gemm_kernel<<<g1, 256>>>(x, b1);

    conv2_est_kernel<<<B_, 256>>>(w2, b2, seq_lens);

    select_kernel<<<1, 32>>>(seq_lens, out, (long long)KSEL * max_time * D_, has_lens);

    long long n4 = (long long)max_time * (D_ / 4);
    dim3 g4((unsigned)((n4 + 255) / 256), KSEL);
    gather_kernel<<<g4, 256>>>(x, out, max_time);
}

// round 3
// speedup vs baseline: 2.9316x; 2.9316x over previous
#include <cuda_runtime.h>
#include <cuda_bf16.h>
#include <cstdint>

// Problem constants
#define B_   64
#define T_   2048
#define D_   512
#define H_   64
#define T1   683      // conv1 output length
#define T2   228      // conv2 output length
#define KDIM 1536     // 3*512
#define NCH  128      // 2*H
#define KSEL 32       // top-k

#define NCHUNK 48     // KDIM / 32
#define BKC    32     // K elems per chunk

// Device scratch
__device__ __nv_bfloat16 g_Wh[NCH * KDIM];  // weights [c][k] hi bf16
__device__ __nv_bfloat16 g_Wl[NCH * KDIM];  // residual lo bf16
__device__ float g_h[(size_t)B_ * T1 * H_];
__device__ float g_est[B_];
__device__ int   g_idx[KSEL];

// ---------------------------------------------------------------------------
// helpers
// ---------------------------------------------------------------------------
__device__ __forceinline__ uint32_t smem_u32(const void* p) {
    uint32_t a;
    asm("{ .reg .u64 t; cvta.to.shared.u64 t, %1; cvt.u32.u64 %0, t; }" : "=r"(a) : "l"(p));
    return a;
}
__device__ __forceinline__ void ldm_x4(uint32_t* r, uint32_t addr) {
    asm volatile("ldmatrix.sync.aligned.m8n8.x4.shared.b16 {%0,%1,%2,%3}, [%4];"
                 : "=r"(r[0]), "=r"(r[1]), "=r"(r[2]), "=r"(r[3]) : "r"(addr));
}
__device__ __forceinline__ void mma_bf16(float* d, const uint32_t* a, const uint32_t* b) {
    asm volatile(
        "mma.sync.aligned.m16n8k16.row.col.f32.bf16.bf16.f32 "
        "{%0,%1,%2,%3}, {%4,%5,%6,%7}, {%8,%9}, {%0,%1,%2,%3};"
        : "+f"(d[0]), "+f"(d[1]), "+f"(d[2]), "+f"(d[3])
        : "r"(a[0]), "r"(a[1]), "r"(a[2]), "r"(a[3]), "r"(b[0]), "r"(b[1]));
}
__device__ __forceinline__ uint32_t pack2(float a, float b) {
    __nv_bfloat162 p = __floats2bfloat162_rn(a, b);  // x=a (low), y=b (high)
    return *(uint32_t*)&p;
}

// ---------------------------------------------------------------------------
// K0: transpose + bf16-split w1: w1[c][d][j] -> g_Wh/g_Wl at [c][k=j*512+d]
// ---------------------------------------------------------------------------
__global__ void prep_w_kernel(const float* __restrict__ w1) {
    int o = blockIdx.x * blockDim.x + threadIdx.x;
    if (o >= NCH * KDIM) return;
    int c = o / KDIM;
    int k = o - c * KDIM;
    float w = w1[c * KDIM + (k & 511) * 3 + (k >> 9)];
    __nv_bfloat16 h = __float2bfloat16_rn(w);
    float r = w - __bfloat162float(h);
    g_Wh[o] = h;
    g_Wl[o] = __float2bfloat16_rn(r);
}

// ---------------------------------------------------------------------------
// K1: conv1 as mma.sync bf16 GEMM (2-term split, 3 passes) + bias + pairmax.
// Block tile 128(m=time) x 128(n=chan), K chunks of 32. 256 threads / 8 warps,
// warp tile 64x32. SMEM rows padded to 40 bf16 (80B: 16B-aligned, ldmatrix
// conflict-free). Double-buffered, reg-prefetch pipeline.
// ---------------------------------------------------------------------------
#define ASTRIDE 40
#define OFF_AHI 0
#define OFF_ALO 10240
#define OFF_BHI 20480
#define OFF_BLO 30720
#define STAGE   40960
#define DYN_SMEM (2 * STAGE)

extern __shared__ char dyn_smem[];

__global__ __launch_bounds__(256, 1) void conv1_mma_kernel(
    const float* __restrict__ x, const float* __restrict__ b1)
{
    __shared__ float b1s[NCH];

    const int b   = blockIdx.y;
    const int m0  = blockIdx.x * 128;
    const int tid = threadIdx.x;
    const int wid = tid >> 5;
    const int lid = tid & 31;
    const int warp_m = (wid >> 2) * 64;
    const int warp_n = (wid & 3) * 32;
    const int g   = lid >> 3;   // ldmatrix lane group
    const int lr  = lid & 7;
    const int t4  = lid & 3;
    const int lg  = lid >> 2;   // mma group row

    if (tid < NCH) b1s[tid] = b1[tid];

    const float* xb = x + (size_t)b * T_ * D_;
    const uint32_t sbase = smem_u32(dyn_smem);

    float acc[4][4][4];
#pragma unroll
    for (int i = 0; i < 4; i++)
#pragma unroll
        for (int j = 0; j < 4; j++)
#pragma unroll
            for (int r = 0; r < 4; r++) acc[i][j][r] = 0.f;

    // per-thread load geometry: c4 col group fixed, rows advance by 32
    const int c4   = (tid & 7) * 4;
    const int row0 = tid >> 3;

    float4 ra[4];
    uint2  rbh[4], rbl[4];

    auto load_regs = [&](int k0) {
#pragma unroll
        for (int q = 0; q < 4; q++) {
            int row = row0 + 32 * q;
            int t   = m0 + row;
            int k   = k0 + c4;
            bool va = (t < T1) && !(t == 0 && k < D_);
            ra[q] = va ? *(const float4*)(xb + (size_t)t * KDIM - D_ + k)
                       : make_float4(0.f, 0.f, 0.f, 0.f);
            rbh[q] = *(const uint2*)(g_Wh + (size_t)row * KDIM + k);
            rbl[q] = *(const uint2*)(g_Wl + (size_t)row * KDIM + k);
        }
    };

    auto store_stage = [&](char* S) {
#pragma unroll
        for (int q = 0; q < 4; q++) {
            int row = row0 + 32 * q;
            int off = row * (ASTRIDE * 2) + c4 * 2;
            float4 v = ra[q];
            float h0 = __bfloat162float(__float2bfloat16_rn(v.x));
            float h1 = __bfloat162float(__float2bfloat16_rn(v.y));
            float h2 = __bfloat162float(__float2bfloat16_rn(v.z));
            float h3 = __bfloat162float(__float2bfloat16_rn(v.w));
            uint2 uh, ul;
            uh.x = pack2(h0, h1);
            uh.y = pack2(h2, h3);
            ul.x = pack2(v.x - h0, v.y - h1);
            ul.y = pack2(v.z - h2, v.w - h3);
            *(uint2*)(S + OFF_AHI + off) = uh;
            *(uint2*)(S + OFF_ALO + off) = ul;
            *(uint2*)(S + OFF_BHI + off) = rbh[q];
            *(uint2*)(S + OFF_BLO + off) = rbl[q];
        }
    };

    // prologue
    load_regs(0);
    store_stage(dyn_smem);
    __syncthreads();

    for (int c = 0; c < NCHUNK; c++) {
        const int buf = c & 1;
        char* S = dyn_smem + buf * STAGE;
        const uint32_t s0 = sbase + buf * STAGE;

        if (c + 1 < NCHUNK) load_regs((c + 1) * BKC);

#pragma unroll
        for (int kh = 0; kh < 2; kh++) {
            uint32_t ah[4][4], al[4][4], bh[4][2], bl[4][2];
            // A fragments: per mtile, 16x16 tile via ldmatrix.x4
            const int akoff = kh * 16 + (g >> 1) * 8;
#pragma unroll
            for (int mi = 0; mi < 4; mi++) {
                int arow = warp_m + mi * 16 + (g & 1) * 8 + lr;
                uint32_t ao = (uint32_t)(arow * (ASTRIDE * 2) + akoff * 2);
                ldm_x4(ah[mi], s0 + OFF_AHI + ao);
                ldm_x4(al[mi], s0 + OFF_ALO + ao);
            }
            // B fragments: 2 ntiles per ldmatrix.x4
            const int bkoff = kh * 16 + (g & 1) * 8;
#pragma unroll
            for (int np = 0; np < 2; np++) {
                int brow = warp_n + np * 16 + (g >> 1) * 8 + lr;
                uint32_t bo = (uint32_t)(brow * (ASTRIDE * 2) + bkoff * 2);
                uint32_t t0[4], t1[4];
                ldm_x4(t0, s0 + OFF_BHI + bo);
                ldm_x4(t1, s0 + OFF_BLO + bo);
                bh[2 * np][0] = t0[0]; bh[2 * np][1] = t0[1];
                bh[2 * np + 1][0] = t0[2]; bh[2 * np + 1][1] = t0[3];
                bl[2 * np][0] = t1[0]; bl[2 * np][1] = t1[1];
                bl[2 * np + 1][0] = t1[2]; bl[2 * np + 1][1] = t1[3];
            }
#pragma unroll
            for (int mi = 0; mi < 4; mi++)
#pragma unroll
                for (int ni = 0; ni < 4; ni++) {
                    mma_bf16(acc[mi][ni], ah[mi], bh[ni]);
                    mma_bf16(acc[mi][ni], ah[mi], bl[ni]);
                    mma_bf16(acc[mi][ni], al[mi], bh[ni]);
                }
        }

        if (c + 1 < NCHUNK) store_stage(dyn_smem + (buf ^ 1) * STAGE);
        __syncthreads();
    }

    // epilogue: bias + pair-maxpool, write g_h[b][t][h]
#pragma unroll
    for (int mi = 0; mi < 4; mi++) {
        int r0 = m0 + warp_m + mi * 16 + lg;
        int r1 = r0 + 8;
#pragma unroll
        for (int ni = 0; ni < 4; ni++) {
            int col = warp_n + ni * 8 + t4 * 2;
            int h   = col >> 1;
            float bb0 = b1s[col], bb1 = b1s[col + 1];
            if (r0 < T1)
                g_h[((size_t)b * T1 + r0) * H_ + h] =
                    fmaxf(acc[mi][ni][0] + bb0, acc[mi][ni][1] + bb1);
            if (r1 < T1)
                g_h[((size_t)b * T1 + r1) * H_ + h] =
                    fmaxf(acc[mi][ni][2] + bb0, acc[mi][ni][3] + bb1);
        }
    }
}

// ---------------------------------------------------------------------------
// K2: conv2 (64ch -> 1, K=3, stride 3, pad 1) + per-batch score reduction
// ---------------------------------------------------------------------------
__global__ void conv2_est_kernel(const float* __restrict__ w2,
                                 const float* __restrict__ b2,
                                 const int* __restrict__ seq_lens)
{
    const int b   = blockIdx.x;
    const int tid = threadIdx.x;
    __shared__ float w2s[H_ * 3];
    __shared__ float red[256];

    if (tid < H_ * 3) w2s[tid] = w2[tid];
    __syncthreads();

    float s = 0.f;
    if (tid < T2) {
        s = b2[0];
#pragma unroll
        for (int kk = 0; kk < 3; kk++) {
            int tp = tid * 3 - 1 + kk;
            if (tp >= 0 && tp < T1) {
                const float* hrow = &g_h[((size_t)b * T1 + tp) * H_];
#pragma unroll 8
                for (int hh = 0; hh < H_; hh++)
                    s += w2s[hh * 3 + kk] * hrow[hh];
            }
        }
    }
    red[tid] = s;
    __syncthreads();
    for (int off = 128; off > 0; off >>= 1) {
        if (tid < off) red[tid] += red[tid + off];
        __syncthreads();
    }
    if (tid == 0) {
        int L   = seq_lens[b];
        int sl1 = (L + 2) / 3;
        int sl2 = (sl1 + 2) / 3;
        g_est[b] = red[0] / (float)sl2;
    }
}

// ---------------------------------------------------------------------------
// K3: parallel top-32 select (jax tie-break: lower index wins), ascending idx
// ---------------------------------------------------------------------------
__global__ void select_kernel(const int* __restrict__ seq_lens,
                              float* __restrict__ out,
                              long long lens_off, int has_lens)
{
    __shared__ float es[B_];
    __shared__ int   rk[B_];
    int i = threadIdx.x;
    es[i] = g_est[i];
    __syncthreads();
    float ei = es[i];
    int r = 0;
#pragma unroll
    for (int j = 0; j < B_; j++) {
        float ej = es[j];
        if (ej > ei || (ej == ei && j < i)) r++;
    }
    rk[i] = r;
    __syncthreads();
    if (rk[i] < KSEL) {
        int slot = 0;
        for (int j = 0; j < i; j++)
            if (rk[j] < KSEL) slot++;
        g_idx[slot] = i;
        if (has_lens) out[lens_off + slot] = (float)seq_lens[i];
    }
}

// ---------------------------------------------------------------------------
// K4: gather x_sel = x[idx][:, :max_time, :]
// ---------------------------------------------------------------------------
__global__ void gather_kernel(const float* __restrict__ x,
                              float* __restrict__ out, int max_time)
{
    const int s = blockIdx.y;
    long long n4 = (long long)max_time * (D_ / 4);
    long long i  = (long long)blockIdx.x * blockDim.x + threadIdx.x;
    if (i >= n4) return;
    int src_b = g_idx[s];
    const float4* src = (const float4*)(x + (size_t)src_b * T_ * D_);
    float4*       dst = (float4*)(out + (size_t)s * max_time * D_);
    dst[i] = src[i];
}

// ---------------------------------------------------------------------------
// Host launcher
// ---------------------------------------------------------------------------
extern "C" void kernel_launch(void* const* d_in, const int* in_sizes, int n_in,
                              void* d_out, int out_size)
{
    const float* x        = (const float*)d_in[0];
    const int*   seq_lens = (const int*)  d_in[1];
    const float* w1       = (const float*)d_in[2];
    const float* b1       = (const float*)d_in[3];
    const float* w2       = (const float*)d_in[4];
    const float* b2       = (const float*)d_in[5];
    float* out = (float*)d_out;

    const long long row_elems = (long long)KSEL * D_;
    int has_lens = ((long long)out_size % row_elems) != 0;
    long long mt = has_lens ? ((long long)out_size - KSEL) / row_elems
                            : (long long)out_size / row_elems;
    int max_time = (int)mt;

    cudaFuncSetAttribute(conv1_mma_kernel,
                         cudaFuncAttributeMaxDynamicSharedMemorySize, DYN_SMEM);

    prep_w_kernel<<<(NCH * KDIM + 255) / 256, 256>>>(w1);

    dim3 g1((T1 + 127) / 128, B_);
    conv1_mma_kernel<<<g1, 256, DYN_SMEM>>>(x, b1);

    conv2_est_kernel<<<B_, 256>>>(w2, b2, seq_lens);

    select_kernel<<<1, B_>>>(seq_lens, out, (long long)KSEL * max_time * D_, has_lens);

    long long n4 = (long long)max_time * (D_ / 4);
    dim3 g4((unsigned)((n4 + 255) / 256), KSEL);
    gather_kernel<<<g4, 256>>>(x, out, max_time);
}

// round 4
// speedup vs baseline: 3.4097x; 1.1631x over previous
#include <cuda_runtime.h>
#include <cuda_fp16.h>
#include <cstdint>

// Problem constants
#define B_   64
#define T_   2048
#define D_   512
#define H_   64
#define T1   683      // conv1 output length
#define T2   228      // conv2 output length
#define KDIM 1536     // 3*512
#define NCH  128      // 2*H
#define KSEL 32       // top-k

#define NCHUNK 48     // KDIM / 32
#define BKC    32     // K elems per chunk

// Device scratch
__device__ __half g_Wh[NCH * KDIM];   // weights [c][k] fp16
__device__ float g_h[(size_t)B_ * T1 * H_];
__device__ float g_est[B_];
__device__ int   g_idx[KSEL];

// ---------------------------------------------------------------------------
// helpers
// ---------------------------------------------------------------------------
__device__ __forceinline__ uint32_t smem_u32(const void* p) {
    uint32_t a;
    asm("{ .reg .u64 t; cvta.to.shared.u64 t, %1; cvt.u32.u64 %0, t; }" : "=r"(a) : "l"(p));
    return a;
}
__device__ __forceinline__ void ldm_x4(uint32_t* r, uint32_t addr) {
    asm volatile("ldmatrix.sync.aligned.m8n8.x4.shared.b16 {%0,%1,%2,%3}, [%4];"
                 : "=r"(r[0]), "=r"(r[1]), "=r"(r[2]), "=r"(r[3]) : "r"(addr));
}
__device__ __forceinline__ void mma_f16(float* d, const uint32_t* a, const uint32_t* b) {
    asm volatile(
        "mma.sync.aligned.m16n8k16.row.col.f32.f16.f16.f32 "
        "{%0,%1,%2,%3}, {%4,%5,%6,%7}, {%8,%9}, {%0,%1,%2,%3};"
        : "+f"(d[0]), "+f"(d[1]), "+f"(d[2]), "+f"(d[3])
        : "r"(a[0]), "r"(a[1]), "r"(a[2]), "r"(a[3]), "r"(b[0]), "r"(b[1]));
}
__device__ __forceinline__ uint32_t packh2(float a, float b) {
    __half2 p = __floats2half2_rn(a, b);
    return *(uint32_t*)&p;
}

// ---------------------------------------------------------------------------
// K0: transpose w1 to fp16: w1[c][d][j] -> g_Wh[c][k=j*512+d]
// ---------------------------------------------------------------------------
__global__ void prep_w_kernel(const float* __restrict__ w1) {
    int o = blockIdx.x * blockDim.x + threadIdx.x;
    if (o >= NCH * KDIM) return;
    int c = o / KDIM;
    int k = o - c * KDIM;
    float w = w1[c * KDIM + (k & 511) * 3 + (k >> 9)];
    g_Wh[o] = __float2half_rn(w);
}

// ---------------------------------------------------------------------------
// K1: conv1 as mma.sync fp16 GEMM, 2-pass split (Ah*B + Al*B) + bias + pairmax.
// Block tile 128(m=time) x 128(n=chan), K chunks of 32. 256 threads / 8 warps,
// warp tile 64x32. SMEM rows padded to 40 halves (80B). Double-buffered,
// register-prefetch pipeline.
// ---------------------------------------------------------------------------
#define ASTRIDE 40
#define OFF_AHI 0
#define OFF_ALO 10240
#define OFF_BHI 20480
#define STAGE   30720
#define DYN_SMEM (2 * STAGE)

extern __shared__ char dyn_smem[];

__global__ __launch_bounds__(256, 1) void conv1_mma_kernel(
    const float* __restrict__ x, const float* __restrict__ b1)
{
    __shared__ float b1s[NCH];

    const int b   = blockIdx.y;
    const int m0  = blockIdx.x * 128;
    const int tid = threadIdx.x;
    const int wid = tid >> 5;
    const int lid = tid & 31;
    const int warp_m = (wid >> 2) * 64;
    const int warp_n = (wid & 3) * 32;
    const int g   = lid >> 3;   // ldmatrix lane group
    const int lr  = lid & 7;
    const int t4  = lid & 3;
    const int lg  = lid >> 2;   // mma group row

    if (tid < NCH) b1s[tid] = b1[tid];

    const float* xb = x + (size_t)b * T_ * D_;
    const uint32_t sbase = smem_u32(dyn_smem);

    float acc[4][4][4];
#pragma unroll
    for (int i = 0; i < 4; i++)
#pragma unroll
        for (int j = 0; j < 4; j++)
#pragma unroll
            for (int r = 0; r < 4; r++) acc[i][j][r] = 0.f;

    // per-thread load geometry
    const int c4   = (tid & 7) * 4;
    const int row0 = tid >> 3;

    float4 ra[4];
    uint2  rbh[4];

    auto load_regs = [&](int k0) {
#pragma unroll
        for (int q = 0; q < 4; q++) {
            int row = row0 + 32 * q;
            int t   = m0 + row;
            int k   = k0 + c4;
            bool va = (t < T1) && !(t == 0 && k < D_);
            ra[q] = va ? *(const float4*)(xb + (size_t)t * KDIM - D_ + k)
                       : make_float4(0.f, 0.f, 0.f, 0.f);
            rbh[q] = *(const uint2*)(g_Wh + (size_t)row * KDIM + k);
        }
    };

    auto store_stage = [&](char* S) {
#pragma unroll
        for (int q = 0; q < 4; q++) {
            int row = row0 + 32 * q;
            int off = row * (ASTRIDE * 2) + c4 * 2;
            float4 v = ra[q];
            float h0 = __half2float(__float2half_rn(v.x));
            float h1 = __half2float(__float2half_rn(v.y));
            float h2 = __half2float(__float2half_rn(v.z));
            float h3 = __half2float(__float2half_rn(v.w));
            uint2 uh, ul;
            uh.x = packh2(h0, h1);
            uh.y = packh2(h2, h3);
            ul.x = packh2(v.x - h0, v.y - h1);
            ul.y = packh2(v.z - h2, v.w - h3);
            *(uint2*)(S + OFF_AHI + off) = uh;
            *(uint2*)(S + OFF_ALO + off) = ul;
            *(uint2*)(S + OFF_BHI + off) = rbh[q];
        }
    };

    // prologue
    load_regs(0);
    store_stage(dyn_smem);
    __syncthreads();

    for (int c = 0; c < NCHUNK; c++) {
        const int buf = c & 1;
        const uint32_t s0 = sbase + buf * STAGE;

        if (c + 1 < NCHUNK) load_regs((c + 1) * BKC);

#pragma unroll
        for (int kh = 0; kh < 2; kh++) {
            uint32_t ah[4][4], al[4][4], bh[4][2];
            const int akoff = kh * 16 + (g >> 1) * 8;
#pragma unroll
            for (int mi = 0; mi < 4; mi++) {
                int arow = warp_m + mi * 16 + (g & 1) * 8 + lr;
                uint32_t ao = (uint32_t)(arow * (ASTRIDE * 2) + akoff * 2);
                ldm_x4(ah[mi], s0 + OFF_AHI + ao);
                ldm_x4(al[mi], s0 + OFF_ALO + ao);
            }
            const int bkoff = kh * 16 + (g & 1) * 8;
#pragma unroll
            for (int np = 0; np < 2; np++) {
                int brow = warp_n + np * 16 + (g >> 1) * 8 + lr;
                uint32_t bo = (uint32_t)(brow * (ASTRIDE * 2) + bkoff * 2);
                uint32_t t0[4];
                ldm_x4(t0, s0 + OFF_BHI + bo);
                bh[2 * np][0] = t0[0]; bh[2 * np][1] = t0[1];
                bh[2 * np + 1][0] = t0[2]; bh[2 * np + 1][1] = t0[3];
            }
#pragma unroll
            for (int mi = 0; mi < 4; mi++)
#pragma unroll
                for (int ni = 0; ni < 4; ni++) {
                    mma_f16(acc[mi][ni], ah[mi], bh[ni]);
                    mma_f16(acc[mi][ni], al[mi], bh[ni]);
                }
        }

        if (c + 1 < NCHUNK) store_stage(dyn_smem + (buf ^ 1) * STAGE);
        __syncthreads();
    }

    // epilogue: bias + pair-maxpool, write g_h[b][t][h]
#pragma unroll
    for (int mi = 0; mi < 4; mi++) {
        int r0 = m0 + warp_m + mi * 16 + lg;
        int r1 = r0 + 8;
#pragma unroll
        for (int ni = 0; ni < 4; ni++) {
            int col = warp_n + ni * 8 + t4 * 2;
            int h   = col >> 1;
            float bb0 = b1s[col], bb1 = b1s[col + 1];
            if (r0 < T1)
                g_h[((size_t)b * T1 + r0) * H_ + h] =
                    fmaxf(acc[mi][ni][0] + bb0, acc[mi][ni][1] + bb1);
            if (r1 < T1)
                g_h[((size_t)b * T1 + r1) * H_ + h] =
                    fmaxf(acc[mi][ni][2] + bb0, acc[mi][ni][3] + bb1);
        }
    }
}

// ---------------------------------------------------------------------------
// K2: conv2 (64ch -> 1, K=3, stride 3, pad 1) + per-batch score reduction
// ---------------------------------------------------------------------------
__global__ void conv2_est_kernel(const float* __restrict__ w2,
                                 const float* __restrict__ b2,
                                 const int* __restrict__ seq_lens)
{
    const int b   = blockIdx.x;
    const int tid = threadIdx.x;
    __shared__ float w2s[H_ * 3];
    __shared__ float red[256];

    if (tid < H_ * 3) w2s[tid] = w2[tid];
    __syncthreads();

    float s = 0.f;
    if (tid < T2) {
        s = b2[0];
#pragma unroll
        for (int kk = 0; kk < 3; kk++) {
            int tp = tid * 3 - 1 + kk;
            if (tp >= 0 && tp < T1) {
                const float* hrow = &g_h[((size_t)b * T1 + tp) * H_];
#pragma unroll 8
                for (int hh = 0; hh < H_; hh++)
                    s += w2s[hh * 3 + kk] * hrow[hh];
            }
        }
    }
    red[tid] = s;
    __syncthreads();
    for (int off = 128; off > 0; off >>= 1) {
        if (tid < off) red[tid] += red[tid + off];
        __syncthreads();
    }
    if (tid == 0) {
        int L   = seq_lens[b];
        int sl1 = (L + 2) / 3;
        int sl2 = (sl1 + 2) / 3;
        g_est[b] = red[0] / (float)sl2;
    }
}

// ---------------------------------------------------------------------------
// K3: parallel top-32 select (jax tie-break: lower index wins), ascending idx
// ---------------------------------------------------------------------------
__global__ void select_kernel(const int* __restrict__ seq_lens,
                              float* __restrict__ out,
                              long long lens_off, int has_lens)
{
    __shared__ float es[B_];
    __shared__ int   rk[B_];
    int i = threadIdx.x;
    es[i] = g_est[i];
    __syncthreads();
    float ei = es[i];
    int r = 0;
#pragma unroll
    for (int j = 0; j < B_; j++) {
        float ej = es[j];
        if (ej > ei || (ej == ei && j < i)) r++;
    }
    rk[i] = r;
    __syncthreads();
    if (rk[i] < KSEL) {
        int slot = 0;
        for (int j = 0; j < i; j++)
            if (rk[j] < KSEL) slot++;
        g_idx[slot] = i;
        if (has_lens) out[lens_off + slot] = (float)seq_lens[i];
    }
}

// ---------------------------------------------------------------------------
// K4: gather x_sel = x[idx][:, :max_time, :]
// ---------------------------------------------------------------------------
__global__ void gather_kernel(const float* __restrict__ x,
                              float* __restrict__ out, int max_time)
{
    const int s = blockIdx.y;
    long long n4 = (long long)max_time * (D_ / 4);
    long long i  = (long long)blockIdx.x * blockDim.x + threadIdx.x;
    if (i >= n4) return;
    int src_b = g_idx[s];
    const float4* src = (const float4*)(x + (size_t)src_b * T_ * D_);
    float4*       dst = (float4*)(out + (size_t)s * max_time * D_);
    dst[i] = src[i];
}

// ---------------------------------------------------------------------------
// Host launcher
// ---------------------------------------------------------------------------
extern "C" void kernel_launch(void* const* d_in, const int* in_sizes, int n_in,
                              void* d_out, int out_size)
{
    const float* x        = (const float*)d_in[0];
    const int*   seq_lens = (const int*)  d_in[1];
    const float* w1       = (const float*)d_in[2];
    const float* b1       = (const float*)d_in[3];
    const float* w2       = (const float*)d_in[4];
    const float* b2       = (const float*)d_in[5];
    float* out = (float*)d_out;

    const long long row_elems = (long long)KSEL * D_;
    int has_lens = ((long long)out_size % row_elems) != 0;
    long long mt = has_lens ? ((long long)out_size - KSEL) / row_elems
                            : (long long)out_size / row_elems;
    int max_time = (int)mt;

    cudaFuncSetAttribute(conv1_mma_kernel,
                         cudaFuncAttributeMaxDynamicSharedMemorySize, DYN_SMEM);

    prep_w_kernel<<<(NCH * KDIM + 255) / 256, 256>>>(w1);

    dim3 g1((T1 + 127) / 128, B_);
    conv1_mma_kernel<<<g1, 256, DYN_SMEM>>>(x, b1);

    conv2_est_kernel<<<B_, 256>>>(w2, b2, seq_lens);

    select_kernel<<<1, B_>>>(seq_lens, out, (long long)KSEL * max_time * D_, has_lens);

    long long n4 = (long long)max_time * (D_ / 4);
    dim3 g4((unsigned)((n4 + 255) / 256), KSEL);
    gather_kernel<<<g4, 256>>>(x, out, max_time);
}

// round 5
// speedup vs baseline: 3.5521x; 1.0418x over previous
#include <cuda_runtime.h>
#include <cuda_fp16.h>
#include <cstdint>

// Problem constants
#define B_   64
#define T_   2048
#define D_   512
#define H_   64
#define T1   683      // conv1 output length
#define T2   228      // conv2 output length
#define KDIM 1536     // 3*512
#define NCH  128      // 2*H
#define KSEL 32       // top-k

#define NCHUNK 48     // KDIM / 32
#define BKC    32     // K elems per chunk

// Device scratch
__device__ __half g_Wh[NCH * KDIM];   // weights [c][k] fp16
__device__ float g_h[(size_t)B_ * T1 * H_];
__device__ float g_est[B_];
__device__ int   g_idx[KSEL];

// ---------------------------------------------------------------------------
// helpers
// ---------------------------------------------------------------------------
__device__ __forceinline__ uint32_t smem_u32(const void* p) {
    uint32_t a;
    asm("{ .reg .u64 t; cvta.to.shared.u64 t, %1; cvt.u32.u64 %0, t; }" : "=r"(a) : "l"(p));
    return a;
}
__device__ __forceinline__ void ldm_x4(uint32_t* r, uint32_t addr) {
    asm volatile("ldmatrix.sync.aligned.m8n8.x4.shared.b16 {%0,%1,%2,%3}, [%4];"
                 : "=r"(r[0]), "=r"(r[1]), "=r"(r[2]), "=r"(r[3]) : "r"(addr));
}
__device__ __forceinline__ void mma_f16(float* d, const uint32_t* a, const uint32_t* b) {
    asm volatile(
        "mma.sync.aligned.m16n8k16.row.col.f32.f16.f16.f32 "
        "{%0,%1,%2,%3}, {%4,%5,%6,%7}, {%8,%9}, {%0,%1,%2,%3};"
        : "+f"(d[0]), "+f"(d[1]), "+f"(d[2]), "+f"(d[3])
        : "r"(a[0]), "r"(a[1]), "r"(a[2]), "r"(a[3]), "r"(b[0]), "r"(b[1]));
}
__device__ __forceinline__ uint32_t packh2(float a, float b) {
    __half2 p = __floats2half2_rn(a, b);
    return *(uint32_t*)&p;
}

// ---------------------------------------------------------------------------
// K0: transpose w1 to fp16: w1[c][d][j] -> g_Wh[c][k=j*512+d]
// ---------------------------------------------------------------------------
__global__ void prep_w_kernel(const float* __restrict__ w1) {
    int o = blockIdx.x * blockDim.x + threadIdx.x;
    if (o >= NCH * KDIM) return;
    int c = o / KDIM;
    int k = o - c * KDIM;
    float w = w1[c * KDIM + (k & 511) * 3 + (k >> 9)];
    g_Wh[o] = __float2half_rn(w);
}

// ---------------------------------------------------------------------------
// K1: conv1 as single-pass fp16 mma.sync GEMM + bias + pair-maxpool.
// Block tile 128(m=time) x 128(n=chan), K chunks of 32. 256 threads / 8 warps,
// warp tile 64x32. SMEM rows padded to 40 halves (80B). Double-buffered,
// register-prefetch pipeline.
// ---------------------------------------------------------------------------
#define ASTRIDE 40
#define OFF_AHI 0
#define OFF_BHI 10240
#define STAGE   20480
#define DYN_SMEM (2 * STAGE)

extern __shared__ char dyn_smem[];

__global__ __launch_bounds__(256, 1) void conv1_mma_kernel(
    const float* __restrict__ x, const float* __restrict__ b1)
{
    __shared__ float b1s[NCH];

    const int b   = blockIdx.y;
    const int m0  = blockIdx.x * 128;
    const int tid = threadIdx.x;
    const int wid = tid >> 5;
    const int lid = tid & 31;
    const int warp_m = (wid >> 2) * 64;
    const int warp_n = (wid & 3) * 32;
    const int g   = lid >> 3;   // ldmatrix lane group
    const int lr  = lid & 7;
    const int t4  = lid & 3;
    const int lg  = lid >> 2;   // mma group row

    if (tid < NCH) b1s[tid] = b1[tid];

    const float* xb = x + (size_t)b * T_ * D_;
    const uint32_t sbase = smem_u32(dyn_smem);

    float acc[4][4][4];
#pragma unroll
    for (int i = 0; i < 4; i++)
#pragma unroll
        for (int j = 0; j < 4; j++)
#pragma unroll
            for (int r = 0; r < 4; r++) acc[i][j][r] = 0.f;

    // per-thread load geometry
    const int c4   = (tid & 7) * 4;
    const int row0 = tid >> 3;

    float4 ra[4];
    uint2  rbh[4];

    auto load_regs = [&](int k0) {
#pragma unroll
        for (int q = 0; q < 4; q++) {
            int row = row0 + 32 * q;
            int t   = m0 + row;
            int k   = k0 + c4;
            bool va = (t < T1) && !(t == 0 && k < D_);
            ra[q] = va ? *(const float4*)(xb + (size_t)t * KDIM - D_ + k)
                       : make_float4(0.f, 0.f, 0.f, 0.f);
            rbh[q] = *(const uint2*)(g_Wh + (size_t)row * KDIM + k);
        }
    };

    auto store_stage = [&](char* S) {
#pragma unroll
        for (int q = 0; q < 4; q++) {
            int row = row0 + 32 * q;
            int off = row * (ASTRIDE * 2) + c4 * 2;
            float4 v = ra[q];
            uint2 uh;
            uh.x = packh2(v.x, v.y);
            uh.y = packh2(v.z, v.w);
            *(uint2*)(S + OFF_AHI + off) = uh;
            *(uint2*)(S + OFF_BHI + off) = rbh[q];
        }
    };

    // prologue
    load_regs(0);
    store_stage(dyn_smem);
    __syncthreads();

    for (int c = 0; c < NCHUNK; c++) {
        const int buf = c & 1;
        const uint32_t s0 = sbase + buf * STAGE;

        if (c + 1 < NCHUNK) load_regs((c + 1) * BKC);

#pragma unroll
        for (int kh = 0; kh < 2; kh++) {
            uint32_t ah[4][4], bh[4][2];
            const int akoff = kh * 16 + (g >> 1) * 8;
#pragma unroll
            for (int mi = 0; mi < 4; mi++) {
                int arow = warp_m + mi * 16 + (g & 1) * 8 + lr;
                uint32_t ao = (uint32_t)(arow * (ASTRIDE * 2) + akoff * 2);
                ldm_x4(ah[mi], s0 + OFF_AHI + ao);
            }
            const int bkoff = kh * 16 + (g & 1) * 8;
#pragma unroll
            for (int np = 0; np < 2; np++) {
                int brow = warp_n + np * 16 + (g >> 1) * 8 + lr;
                uint32_t bo = (uint32_t)(brow * (ASTRIDE * 2) + bkoff * 2);
                uint32_t t0[4];
                ldm_x4(t0, s0 + OFF_BHI + bo);
                bh[2 * np][0] = t0[0]; bh[2 * np][1] = t0[1];
                bh[2 * np + 1][0] = t0[2]; bh[2 * np + 1][1] = t0[3];
            }
#pragma unroll
            for (int mi = 0; mi < 4; mi++)
#pragma unroll
                for (int ni = 0; ni < 4; ni++)
                    mma_f16(acc[mi][ni], ah[mi], bh[ni]);
        }

        if (c + 1 < NCHUNK) store_stage(dyn_smem + (buf ^ 1) * STAGE);
        __syncthreads();
    }

    // epilogue: bias + pair-maxpool, write g_h[b][t][h]
#pragma unroll
    for (int mi = 0; mi < 4; mi++) {
        int r0 = m0 + warp_m + mi * 16 + lg;
        int r1 = r0 + 8;
#pragma unroll
        for (int ni = 0; ni < 4; ni++) {
            int col = warp_n + ni * 8 + t4 * 2;
            int h   = col >> 1;
            float bb0 = b1s[col], bb1 = b1s[col + 1];
            if (r0 < T1)
                g_h[((size_t)b * T1 + r0) * H_ + h] =
                    fmaxf(acc[mi][ni][0] + bb0, acc[mi][ni][1] + bb1);
            if (r1 < T1)
                g_h[((size_t)b * T1 + r1) * H_ + h] =
                    fmaxf(acc[mi][ni][2] + bb0, acc[mi][ni][3] + bb1);
        }
    }
}

// ---------------------------------------------------------------------------
// K2: conv2 (64ch -> 1, K=3, stride 3, pad 1) + per-batch score reduction
// ---------------------------------------------------------------------------
__global__ void conv2_est_kernel(const float* __restrict__ w2,
                                 const float* __restrict__ b2,
                                 const int* __restrict__ seq_lens)
{
    const int b   = blockIdx.x;
    const int tid = threadIdx.x;
    __shared__ float w2s[H_ * 3];
    __shared__ float red[256];

    if (tid < H_ * 3) w2s[tid] = w2[tid];
    __syncthreads();

    float s = 0.f;
    if (tid < T2) {
        s = b2[0];
#pragma unroll
        for (int kk = 0; kk < 3; kk++) {
            int tp = tid * 3 - 1 + kk;
            if (tp >= 0 && tp < T1) {
                const float* hrow = &g_h[((size_t)b * T1 + tp) * H_];
#pragma unroll 8
                for (int hh = 0; hh < H_; hh++)
                    s += w2s[hh * 3 + kk] * hrow[hh];
            }
        }
    }
    red[tid] = s;
    __syncthreads();
    for (int off = 128; off > 0; off >>= 1) {
        if (tid < off) red[tid] += red[tid + off];
        __syncthreads();
    }
    if (tid == 0) {
        int L   = seq_lens[b];
        int sl1 = (L + 2) / 3;
        int sl2 = (sl1 + 2) / 3;
        g_est[b] = red[0] / (float)sl2;
    }
}

// ---------------------------------------------------------------------------
// K3: parallel top-32 select (jax tie-break: lower index wins), ascending idx
// ---------------------------------------------------------------------------
__global__ void select_kernel(const int* __restrict__ seq_lens,
                              float* __restrict__ out,
                              long long lens_off, int has_lens)
{
    __shared__ float es[B_];
    __shared__ int   rk[B_];
    int i = threadIdx.x;
    es[i] = g_est[i];
    __syncthreads();
    float ei = es[i];
    int r = 0;
#pragma unroll
    for (int j = 0; j < B_; j++) {
        float ej = es[j];
        if (ej > ei || (ej == ei && j < i)) r++;
    }
    rk[i] = r;
    __syncthreads();
    if (rk[i] < KSEL) {
        int slot = 0;
        for (int j = 0; j < i; j++)
            if (rk[j] < KSEL) slot++;
        g_idx[slot] = i;
        if (has_lens) out[lens_off + slot] = (float)seq_lens[i];
    }
}

// ---------------------------------------------------------------------------
// K4: gather x_sel = x[idx][:, :max_time, :]
// ---------------------------------------------------------------------------
__global__ void gather_kernel(const float* __restrict__ x,
                              float* __restrict__ out, int max_time)
{
    const int s = blockIdx.y;
    long long n4 = (long long)max_time * (D_ / 4);
    long long i  = (long long)blockIdx.x * blockDim.x + threadIdx.x;
    if (i >= n4) return;
    int src_b = g_idx[s];
    const float4* src = (const float4*)(x + (size_t)src_b * T_ * D_);
    float4*       dst = (float4*)(out + (size_t)s * max_time * D_);
    dst[i] = src[i];
}

// ---------------------------------------------------------------------------
// Host launcher
// ---------------------------------------------------------------------------
extern "C" void kernel_launch(void* const* d_in, const int* in_sizes, int n_in,
                              void* d_out, int out_size)
{
    const float* x        = (const float*)d_in[0];
    const int*   seq_lens = (const int*)  d_in[1];
    const float* w1       = (const float*)d_in[2];
    const float* b1       = (const float*)d_in[3];
    const float* w2       = (const float*)d_in[4];
    const float* b2       = (const float*)d_in[5];
    float* out = (float*)d_out;

    const long long row_elems = (long long)KSEL * D_;
    int has_lens = ((long long)out_size % row_elems) != 0;
    long long mt = has_lens ? ((long long)out_size - KSEL) / row_elems
                            : (long long)out_size / row_elems;
    int max_time = (int)mt;

    cudaFuncSetAttribute(conv1_mma_kernel,
                         cudaFuncAttributeMaxDynamicSharedMemorySize, DYN_SMEM);

    prep_w_kernel<<<(NCH * KDIM + 255) / 256, 256>>>(w1);

    dim3 g1((T1 + 127) / 128, B_);
    conv1_mma_kernel<<<g1, 256, DYN_SMEM>>>(x, b1);

    conv2_est_kernel<<<B_, 256>>>(w2, b2, seq_lens);

    select_kernel<<<1, B_>>>(seq_lens, out, (long long)KSEL * max_time * D_, has_lens);

    long long n4 = (long long)max_time * (D_ / 4);
    dim3 g4((unsigned)((n4 + 255) / 256), KSEL);
    gather_kernel<<<g4, 256>>>(x, out, max_time);
}

// round 6
// speedup vs baseline: 4.4920x; 1.2646x over previous
#include <cuda_runtime.h>
#include <cuda_fp16.h>
#include <cstdint>

// Problem constants
#define B_   64
#define T_   2048
#define D_   512
#define H_   64
#define T1   683      // conv1 output length
#define T2   228      // conv2 output length
#define KDIM 1536     // 3*512
#define NCH  128      // 2*H
#define KSEL 32       // top-k

#define NCHUNK 48     // KDIM / 32
#define BKC    32     // K elems per chunk

// Device scratch
__device__ __half g_Wh[NCH * KDIM];   // weights [c][k] fp16
__device__ float g_h[(size_t)B_ * T1 * H_];
__device__ float g_est[B_];
__device__ int   g_idx[KSEL];

// ---------------------------------------------------------------------------
// helpers
// ---------------------------------------------------------------------------
__device__ __forceinline__ uint32_t smem_u32(const void* p) {
    uint32_t a;
    asm("{ .reg .u64 t; cvta.to.shared.u64 t, %1; cvt.u32.u64 %0, t; }" : "=r"(a) : "l"(p));
    return a;
}
__device__ __forceinline__ void ldm_x4(uint32_t* r, uint32_t addr) {
    asm volatile("ldmatrix.sync.aligned.m8n8.x4.shared.b16 {%0,%1,%2,%3}, [%4];"
                 : "=r"(r[0]), "=r"(r[1]), "=r"(r[2]), "=r"(r[3]) : "r"(addr));
}
__device__ __forceinline__ void mma_f16(float* d, const uint32_t* a, const uint32_t* b) {
    asm volatile(
        "mma.sync.aligned.m16n8k16.row.col.f32.f16.f16.f32 "
        "{%0,%1,%2,%3}, {%4,%5,%6,%7}, {%8,%9}, {%0,%1,%2,%3};"
        : "+f"(d[0]), "+f"(d[1]), "+f"(d[2]), "+f"(d[3])
        : "r"(a[0]), "r"(a[1]), "r"(a[2]), "r"(a[3]), "r"(b[0]), "r"(b[1]));
}
__device__ __forceinline__ uint32_t packh2(float a, float b) {
    __half2 p = __floats2half2_rn(a, b);
    return *(uint32_t*)&p;
}
#define CP_ASYNC8(dst, src) \
    asm volatile("cp.async.ca.shared.global [%0], [%1], 8;" :: "r"(dst), "l"(src))
#define CP_COMMIT()  asm volatile("cp.async.commit_group;")
#define CP_WAIT0()   asm volatile("cp.async.wait_group 0;" ::: "memory")

// ---------------------------------------------------------------------------
// K0: transpose w1 to fp16: w1[c][d][j] -> g_Wh[c][k=j*512+d]
// ---------------------------------------------------------------------------
__global__ void prep_w_kernel(const float* __restrict__ w1) {
    int o = blockIdx.x * blockDim.x + threadIdx.x;
    if (o >= NCH * KDIM) return;
    int c = o / KDIM;
    int k = o - c * KDIM;
    float w = w1[c * KDIM + (k & 511) * 3 + (k >> 9)];
    g_Wh[o] = __float2half_rn(w);
}

// ---------------------------------------------------------------------------
// K1: conv1 as single-pass fp16 mma.sync GEMM + bias + pair-maxpool.
// Block tile 128(m) x 128(n), K chunks of 32. 256 threads / 8 warps,
// warp tile 64x32. A via LDG+cvt+STS (double-buffered, reg-prefetch);
// B via cp.async fp16 direct. __launch_bounds__(256,2) for 2 CTAs/SM.
// ---------------------------------------------------------------------------
#define ASTRIDE 40
#define OFF_AHI 0
#define OFF_BHI 10240
#define STAGE   20480
#define DYN_SMEM (2 * STAGE)

extern __shared__ char dyn_smem[];

__global__ __launch_bounds__(256, 2) void conv1_mma_kernel(
    const float* __restrict__ x, const float* __restrict__ b1)
{
    __shared__ float b1s[NCH];

    const int b   = blockIdx.y;
    const int m0  = blockIdx.x * 128;
    const int tid = threadIdx.x;
    const int wid = tid >> 5;
    const int lid = tid & 31;
    const int warp_m = (wid >> 2) * 64;
    const int warp_n = (wid & 3) * 32;
    const int g   = lid >> 3;   // ldmatrix lane group
    const int lr  = lid & 7;
    const int t4  = lid & 3;
    const int lg  = lid >> 2;   // mma group row

    if (tid < NCH) b1s[tid] = b1[tid];

    const float* xb = x + (size_t)b * T_ * D_;
    const uint32_t sbase = smem_u32(dyn_smem);

    float acc[4][4][4];
#pragma unroll
    for (int i = 0; i < 4; i++)
#pragma unroll
        for (int j = 0; j < 4; j++)
#pragma unroll
            for (int r = 0; r < 4; r++) acc[i][j][r] = 0.f;

    // A load geometry: c4 col group (floats), rows advance by 32
    const int c4   = (tid & 7) * 4;
    const int row0 = tid >> 3;

    float4 ra[4];

    auto load_regs = [&](int k0) {
#pragma unroll
        for (int q = 0; q < 4; q++) {
            int row = row0 + 32 * q;
            int t   = m0 + row;
            int k   = k0 + c4;
            bool va = (t < T1) && !(t == 0 && k < D_);
            ra[q] = va ? *(const float4*)(xb + (size_t)t * KDIM - D_ + k)
                       : make_float4(0.f, 0.f, 0.f, 0.f);
        }
    };

    auto store_stageA = [&](char* S) {
#pragma unroll
        for (int q = 0; q < 4; q++) {
            int row = row0 + 32 * q;
            int off = row * (ASTRIDE * 2) + c4 * 2;
            float4 v = ra[q];
            uint2 uh;
            uh.x = packh2(v.x, v.y);
            uh.y = packh2(v.z, v.w);
            *(uint2*)(S + OFF_AHI + off) = uh;
        }
    };

    // B cp.async: 128 rows x 32 halves (64B) per stage, 8B granules
    // e = tid + 256*q, q 0..3 -> row = e>>3, part = e&7
    auto issue_B = [&](uint32_t sdst, int k0) {
#pragma unroll
        for (int q = 0; q < 4; q++) {
            int e    = tid + 256 * q;
            int row  = e >> 3;
            int part = e & 7;
            uint32_t dst = sdst + OFF_BHI + row * (ASTRIDE * 2) + part * 8;
            const __half* src = g_Wh + (size_t)row * KDIM + k0 + part * 4;
            CP_ASYNC8(dst, src);
        }
    };

    // prologue: stage 0
    load_regs(0);
    issue_B(sbase, 0);
    CP_COMMIT();
    store_stageA(dyn_smem);
    CP_WAIT0();
    __syncthreads();

    for (int c = 0; c < NCHUNK; c++) {
        const int buf = c & 1;
        const uint32_t s0 = sbase + buf * STAGE;

        if (c + 1 < NCHUNK) {
            load_regs((c + 1) * BKC);
            issue_B(sbase + (buf ^ 1) * STAGE, (c + 1) * BKC);
            CP_COMMIT();
        }

#pragma unroll
        for (int kh = 0; kh < 2; kh++) {
            uint32_t ah[4][4], bh[4][2];
            const int akoff = kh * 16 + (g >> 1) * 8;
#pragma unroll
            for (int mi = 0; mi < 4; mi++) {
                int arow = warp_m + mi * 16 + (g & 1) * 8 + lr;
                uint32_t ao = (uint32_t)(arow * (ASTRIDE * 2) + akoff * 2);
                ldm_x4(ah[mi], s0 + OFF_AHI + ao);
            }
            const int bkoff = kh * 16 + (g & 1) * 8;
#pragma unroll
            for (int np = 0; np < 2; np++) {
                int brow = warp_n + np * 16 + (g >> 1) * 8 + lr;
                uint32_t bo = (uint32_t)(brow * (ASTRIDE * 2) + bkoff * 2);
                uint32_t t0[4];
                ldm_x4(t0, s0 + OFF_BHI + bo);
                bh[2 * np][0] = t0[0]; bh[2 * np][1] = t0[1];
                bh[2 * np + 1][0] = t0[2]; bh[2 * np + 1][1] = t0[3];
            }
#pragma unroll
            for (int mi = 0; mi < 4; mi++)
#pragma unroll
                for (int ni = 0; ni < 4; ni++)
                    mma_f16(acc[mi][ni], ah[mi], bh[ni]);
        }

        if (c + 1 < NCHUNK) store_stageA(dyn_smem + (buf ^ 1) * STAGE);
        CP_WAIT0();
        __syncthreads();
    }

    // epilogue: bias + pair-maxpool, write g_h[b][t][h]
#pragma unroll
    for (int mi = 0; mi < 4; mi++) {
        int r0 = m0 + warp_m + mi * 16 + lg;
        int r1 = r0 + 8;
#pragma unroll
        for (int ni = 0; ni < 4; ni++) {
            int col = warp_n + ni * 8 + t4 * 2;
            int h   = col >> 1;
            float bb0 = b1s[col], bb1 = b1s[col + 1];
            if (r0 < T1)
                g_h[((size_t)b * T1 + r0) * H_ + h] =
                    fmaxf(acc[mi][ni][0] + bb0, acc[mi][ni][1] + bb1);
            if (r1 < T1)
                g_h[((size_t)b * T1 + r1) * H_ + h] =
                    fmaxf(acc[mi][ni][2] + bb0, acc[mi][ni][3] + bb1);
        }
    }
}

// ---------------------------------------------------------------------------
// K2: conv2 + score reduction, warp-per-t2, coalesced float2 row loads.
// est[b] = (sum_t2 products + T2*b2) / sl2. One block per batch, 8 warps.
// ---------------------------------------------------------------------------
__global__ __launch_bounds__(256) void conv2_est_kernel(
    const float* __restrict__ w2, const float* __restrict__ b2,
    const int* __restrict__ seq_lens)
{
    const int b   = blockIdx.x;
    const int tid = threadIdx.x;
    const int wid = tid >> 5;
    const int lid = tid & 31;
    __shared__ float w2t[3][H_];
    __shared__ float part[8];

    if (tid < H_ * 3) {
        int hh = tid / 3, kk = tid - hh * 3;
        w2t[kk][hh] = w2[tid];
    }
    __syncthreads();

    // per-lane weights for its 2 channels
    float wk0[3], wk1[3];
#pragma unroll
    for (int kk = 0; kk < 3; kk++) {
        wk0[kk] = w2t[kk][2 * lid];
        wk1[kk] = w2t[kk][2 * lid + 1];
    }

    const float* hb = g_h + (size_t)b * T1 * H_;
    float s = 0.f;
    for (int t2 = wid; t2 < T2; t2 += 8) {
        int base = t2 * 3 - 1;
#pragma unroll
        for (int kk = 0; kk < 3; kk++) {
            int tp = base + kk;
            if (tp >= 0) {  // tp < T1 always holds (max 682)
                float2 v = *(const float2*)(hb + (size_t)tp * H_ + 2 * lid);
                s += v.x * wk0[kk] + v.y * wk1[kk];
            }
        }
    }
#pragma unroll
    for (int o = 16; o > 0; o >>= 1)
        s += __shfl_xor_sync(0xFFFFFFFFu, s, o);
    if (lid == 0) part[wid] = s;
    __syncthreads();
    if (tid == 0) {
        float tot = 0.f;
#pragma unroll
        for (int w = 0; w < 8; w++) tot += part[w];
        tot += (float)T2 * b2[0];
        int L   = seq_lens[b];
        int sl1 = (L + 2) / 3;
        int sl2 = (sl1 + 2) / 3;
        g_est[b] = tot / (float)sl2;
    }
}

// ---------------------------------------------------------------------------
// K3: parallel top-32 select (jax tie-break: lower index wins), ascending idx
// ---------------------------------------------------------------------------
__global__ void select_kernel(const int* __restrict__ seq_lens,
                              float* __restrict__ out,
                              long long lens_off, int has_lens)
{
    __shared__ float es[B_];
    __shared__ int   rk[B_];
    int i = threadIdx.x;
    es[i] = g_est[i];
    __syncthreads();
    float ei = es[i];
    int r = 0;
#pragma unroll
    for (int j = 0; j < B_; j++) {
        float ej = es[j];
        if (ej > ei || (ej == ei && j < i)) r++;
    }
    rk[i] = r;
    __syncthreads();
    if (rk[i] < KSEL) {
        int slot = 0;
        for (int j = 0; j < i; j++)
            if (rk[j] < KSEL) slot++;
        g_idx[slot] = i;
        if (has_lens) out[lens_off + slot] = (float)seq_lens[i];
    }
}

// ---------------------------------------------------------------------------
// K4: gather x_sel = x[idx][:, :max_time, :]
// ---------------------------------------------------------------------------
__global__ void gather_kernel(const float* __restrict__ x,
                              float* __restrict__ out, int max_time)
{
    const int s = blockIdx.y;
    long long n4 = (long long)max_time * (D_ / 4);
    long long i  = (long long)blockIdx.x * blockDim.x + threadIdx.x;
    if (i >= n4) return;
    int src_b = g_idx[s];
    const float4* src = (const float4*)(x + (size_t)src_b * T_ * D_);
    float4*       dst = (float4*)(out + (size_t)s * max_time * D_);
    dst[i] = src[i];
}

// ---------------------------------------------------------------------------
// Host launcher
// ---------------------------------------------------------------------------
extern "C" void kernel_launch(void* const* d_in, const int* in_sizes, int n_in,
                              void* d_out, int out_size)
{
    const float* x        = (const float*)d_in[0];
    const int*   seq_lens = (const int*)  d_in[1];
    const float* w1       = (const float*)d_in[2];
    const float* b1       = (const float*)d_in[3];
    const float* w2       = (const float*)d_in[4];
    const float* b2       = (const float*)d_in[5];
    float* out = (float*)d_out;

    const long long row_elems = (long long)KSEL * D_;
    int has_lens = ((long long)out_size % row_elems) != 0;
    long long mt = has_lens ? ((long long)out_size - KSEL) / row_elems
                            : (long long)out_size / row_elems;
    int max_time = (int)mt;

    cudaFuncSetAttribute(conv1_mma_kernel,
                         cudaFuncAttributeMaxDynamicSharedMemorySize, DYN_SMEM);

    prep_w_kernel<<<(NCH * KDIM + 255) / 256, 256>>>(w1);

    dim3 g1((T1 + 127) / 128, B_);
    conv1_mma_kernel<<<g1, 256, DYN_SMEM>>>(x, b1);

    conv2_est_kernel<<<B_, 256>>>(w2, b2, seq_lens);

    select_kernel<<<1, B_>>>(seq_lens, out, (long long)KSEL * max_time * D_, has_lens);

    long long n4 = (long long)max_time * (D_ / 4);
    dim3 g4((unsigned)((n4 + 255) / 256), KSEL);
    gather_kernel<<<g4, 256>>>(x, out, max_time);
}

// round 7
// speedup vs baseline: 5.2652x; 1.1721x over previous
#include <cuda_runtime.h>
#include <cuda_fp16.h>
#include <cstdint>

// Problem constants
#define B_   64
#define T_   2048
#define D_   512
#define H_   64
#define T1   683      // conv1 output length
#define T2   228      // conv2 output length
#define KDIM 1536     // 3*512
#define NCH  128      // 2*H
#define KSEL 32       // top-k

#define NCHUNK 48     // KDIM / 32
#define BKC    32     // K elems per chunk

#define MROWS (B_ * T1)   // 43712 flattened (b,t) rows
#define MTILE 160
#define NTILES ((MROWS + MTILE - 1) / MTILE)   // 274

// Device scratch
__device__ __half g_Wh[NCH * KDIM];   // weights [c][k] fp16
__device__ float g_h[(size_t)MROWS * H_];   // [r = b*683+t][h]
__device__ float g_est[B_];
__device__ int   g_idx[KSEL];

// ---------------------------------------------------------------------------
// helpers
// ---------------------------------------------------------------------------
__device__ __forceinline__ uint32_t smem_u32(const void* p) {
    uint32_t a;
    asm("{ .reg .u64 t; cvta.to.shared.u64 t, %1; cvt.u32.u64 %0, t; }" : "=r"(a) : "l"(p));
    return a;
}
__device__ __forceinline__ void ldm_x4(uint32_t* r, uint32_t addr) {
    asm volatile("ldmatrix.sync.aligned.m8n8.x4.shared.b16 {%0,%1,%2,%3}, [%4];"
                 : "=r"(r[0]), "=r"(r[1]), "=r"(r[2]), "=r"(r[3]) : "r"(addr));
}
__device__ __forceinline__ void mma_f16(float* d, const uint32_t* a, const uint32_t* b) {
    asm volatile(
        "mma.sync.aligned.m16n8k16.row.col.f32.f16.f16.f32 "
        "{%0,%1,%2,%3}, {%4,%5,%6,%7}, {%8,%9}, {%0,%1,%2,%3};"
        : "+f"(d[0]), "+f"(d[1]), "+f"(d[2]), "+f"(d[3])
        : "r"(a[0]), "r"(a[1]), "r"(a[2]), "r"(a[3]), "r"(b[0]), "r"(b[1]));
}
__device__ __forceinline__ uint32_t packh2(float a, float b) {
    __half2 p = __floats2half2_rn(a, b);
    return *(uint32_t*)&p;
}
#define CP_ASYNC8(dst, src) \
    asm volatile("cp.async.ca.shared.global [%0], [%1], 8;" :: "r"(dst), "l"(src))
#define CP_COMMIT()  asm volatile("cp.async.commit_group;")
#define CP_WAIT0()   asm volatile("cp.async.wait_group 0;" ::: "memory")

// ---------------------------------------------------------------------------
// K0: transpose w1 to fp16: w1[c][d][j] -> g_Wh[c][k=j*512+d]
// ---------------------------------------------------------------------------
__global__ void prep_w_kernel(const float* __restrict__ w1) {
    int o = blockIdx.x * blockDim.x + threadIdx.x;
    if (o >= NCH * KDIM) return;
    int c = o / KDIM;
    int k = o - c * KDIM;
    float w = w1[c * KDIM + (k & 511) * 3 + (k >> 9)];
    g_Wh[o] = __float2half_rn(w);
}

// ---------------------------------------------------------------------------
// K1: conv1 as single-pass fp16 mma.sync GEMM over flattened (b,t) rows.
// M-tile 160 x N 128, K chunks of 32. Grid = 274 (single wave at 2 CTA/SM).
// 256 threads / 8 warps as 2(m) x 4(n), warp tile 80x32.
// A: LDG f32x4 -> cvt fp16 packed -> STS (double-buffered, reg prefetch).
// B: cp.async fp16 direct, double-buffered.
// ---------------------------------------------------------------------------
#define ASTRIDE 40                 // halves per smem row (80B)
#define OFF_A   0
#define OFF_B   12800              // 160 * 80
#define STAGE   23040              // + 128 * 80
#define DYN_SMEM (2 * STAGE)

extern __shared__ char dyn_smem[];

__global__ __launch_bounds__(256, 2) void conv1_mma_kernel(
    const float* __restrict__ x, const float* __restrict__ b1)
{
    __shared__ float b1s[NCH];

    const int M0  = blockIdx.x * MTILE;
    const int tid = threadIdx.x;
    const int wid = tid >> 5;
    const int lid = tid & 31;
    const int warp_m = (wid >> 2) * 80;
    const int warp_n = (wid & 3) * 32;
    const int g   = lid >> 3;   // ldmatrix lane group
    const int lr  = lid & 7;
    const int t4  = lid & 3;
    const int lg  = lid >> 2;   // mma group row

    if (tid < NCH) b1s[tid] = b1[tid];

    const uint32_t sbase = smem_u32(dyn_smem);

    float acc[5][4][4];
#pragma unroll
    for (int i = 0; i < 5; i++)
#pragma unroll
        for (int j = 0; j < 4; j++)
#pragma unroll
            for (int r = 0; r < 4; r++) acc[i][j][r] = 0.f;

    // A load geometry: c4 = float col group, rows advance by 32
    const int c4   = (tid & 7) * 4;
    const int row0 = tid >> 3;

    // Precompute per-q row pointers and zero-until-k thresholds
    const float* pq[5];
    int zu[5];
#pragma unroll
    for (int q = 0; q < 5; q++) {
        int row = row0 + 32 * q;
        int r   = M0 + row;
        if (r >= MROWS) {
            zu[q] = KDIM;          // never valid
            pq[q] = x;
        } else {
            int bb = r / T1;
            int tt = r - bb * T1;
            pq[q]  = x + (size_t)bb * T_ * D_ + (size_t)tt * KDIM - D_ + c4;
            zu[q]  = (tt == 0) ? D_ : 0;
        }
    }

    uint2 ra[5];

    auto load_regs = [&](int k0) {
#pragma unroll
        for (int q = 0; q < 5; q++) {
            float4 v = make_float4(0.f, 0.f, 0.f, 0.f);
            if (k0 + c4 >= zu[q]) v = *(const float4*)(pq[q] + k0);
            ra[q].x = packh2(v.x, v.y);
            ra[q].y = packh2(v.z, v.w);
        }
    };

    auto store_stageA = [&](char* S) {
#pragma unroll
        for (int q = 0; q < 5; q++) {
            int row = row0 + 32 * q;
            int off = row * (ASTRIDE * 2) + c4 * 2;
            *(uint2*)(S + OFF_A + off) = ra[q];
        }
    };

    // B cp.async: 128 rows x 32 halves (64B) per stage, 8B granules
    auto issue_B = [&](uint32_t sdst, int k0) {
#pragma unroll
        for (int q = 0; q < 4; q++) {
            int e    = tid + 256 * q;
            int row  = e >> 3;
            int part = e & 7;
            uint32_t dst = sdst + OFF_B + row * (ASTRIDE * 2) + part * 8;
            const __half* src = g_Wh + (size_t)row * KDIM + k0 + part * 4;
            CP_ASYNC8(dst, src);
        }
    };

    // prologue: stage 0
    load_regs(0);
    issue_B(sbase, 0);
    CP_COMMIT();
    store_stageA(dyn_smem);
    CP_WAIT0();
    __syncthreads();

    for (int c = 0; c < NCHUNK; c++) {
        const int buf = c & 1;
        const uint32_t s0 = sbase + buf * STAGE;

        if (c + 1 < NCHUNK) {
            load_regs((c + 1) * BKC);
            issue_B(sbase + (buf ^ 1) * STAGE, (c + 1) * BKC);
            CP_COMMIT();
        }

#pragma unroll
        for (int kh = 0; kh < 2; kh++) {
            uint32_t bh[4][2];
            const int bkoff = kh * 16 + (g & 1) * 8;
#pragma unroll
            for (int np = 0; np < 2; np++) {
                int brow = warp_n + np * 16 + (g >> 1) * 8 + lr;
                uint32_t bo = (uint32_t)(brow * (ASTRIDE * 2) + bkoff * 2);
                uint32_t t0[4];
                ldm_x4(t0, s0 + OFF_B + bo);
                bh[2 * np][0] = t0[0]; bh[2 * np][1] = t0[1];
                bh[2 * np + 1][0] = t0[2]; bh[2 * np + 1][1] = t0[3];
            }
            const int akoff = kh * 16 + (g >> 1) * 8;
#pragma unroll
            for (int mi = 0; mi < 5; mi++) {
                uint32_t ah[4];
                int arow = warp_m + mi * 16 + (g & 1) * 8 + lr;
                uint32_t ao = (uint32_t)(arow * (ASTRIDE * 2) + akoff * 2);
                ldm_x4(ah, s0 + OFF_A + ao);
#pragma unroll
                for (int ni = 0; ni < 4; ni++)
                    mma_f16(acc[mi][ni], ah, bh[ni]);
            }
        }

        if (c + 1 < NCHUNK) store_stageA(dyn_smem + (buf ^ 1) * STAGE);
        CP_WAIT0();
        __syncthreads();
    }

    // epilogue: bias + pair-maxpool, write g_h[r][h]
#pragma unroll
    for (int mi = 0; mi < 5; mi++) {
        int r0 = M0 + warp_m + mi * 16 + lg;
        int r1 = r0 + 8;
#pragma unroll
        for (int ni = 0; ni < 4; ni++) {
            int col = warp_n + ni * 8 + t4 * 2;
            int h   = col >> 1;
            float bb0 = b1s[col], bb1 = b1s[col + 1];
            if (r0 < MROWS)
                g_h[(size_t)r0 * H_ + h] =
                    fmaxf(acc[mi][ni][0] + bb0, acc[mi][ni][1] + bb1);
            if (r1 < MROWS)
                g_h[(size_t)r1 * H_ + h] =
                    fmaxf(acc[mi][ni][2] + bb0, acc[mi][ni][3] + bb1);
        }
    }
}

// ---------------------------------------------------------------------------
// K2: conv2 + score reduction, warp-per-t2, coalesced float2 row loads.
// ---------------------------------------------------------------------------
__global__ __launch_bounds__(256) void conv2_est_kernel(
    const float* __restrict__ w2, const float* __restrict__ b2,
    const int* __restrict__ seq_lens)
{
    const int b   = blockIdx.x;
    const int tid = threadIdx.x;
    const int wid = tid >> 5;
    const int lid = tid & 31;
    __shared__ float w2t[3][H_];
    __shared__ float part[8];

    if (tid < H_ * 3) {
        int hh = tid / 3, kk = tid - hh * 3;
        w2t[kk][hh] = w2[tid];
    }
    __syncthreads();

    float wk0[3], wk1[3];
#pragma unroll
    for (int kk = 0; kk < 3; kk++) {
        wk0[kk] = w2t[kk][2 * lid];
        wk1[kk] = w2t[kk][2 * lid + 1];
    }

    const float* hb = g_h + (size_t)b * T1 * H_;
    float s = 0.f;
    for (int t2 = wid; t2 < T2; t2 += 8) {
        int base = t2 * 3 - 1;
#pragma unroll
        for (int kk = 0; kk < 3; kk++) {
            int tp = base + kk;
            if (tp >= 0) {
                float2 v = *(const float2*)(hb + (size_t)tp * H_ + 2 * lid);
                s += v.x * wk0[kk] + v.y * wk1[kk];
            }
        }
    }
#pragma unroll
    for (int o = 16; o > 0; o >>= 1)
        s += __shfl_xor_sync(0xFFFFFFFFu, s, o);
    if (lid == 0) part[wid] = s;
    __syncthreads();
    if (tid == 0) {
        float tot = 0.f;
#pragma unroll
        for (int w = 0; w < 8; w++) tot += part[w];
        tot += (float)T2 * b2[0];
        int L   = seq_lens[b];
        int sl1 = (L + 2) / 3;
        int sl2 = (sl1 + 2) / 3;
        g_est[b] = tot / (float)sl2;
    }
}

// ---------------------------------------------------------------------------
// K3: parallel top-32 select (jax tie-break: lower index wins), ascending idx
// ---------------------------------------------------------------------------
__global__ void select_kernel(const int* __restrict__ seq_lens,
                              float* __restrict__ out,
                              long long lens_off, int has_lens)
{
    __shared__ float es[B_];
    __shared__ int   rk[B_];
    int i = threadIdx.x;
    es[i] = g_est[i];
    __syncthreads();
    float ei = es[i];
    int r = 0;
#pragma unroll
    for (int j = 0; j < B_; j++) {
        float ej = es[j];
        if (ej > ei || (ej == ei && j < i)) r++;
    }
    rk[i] = r;
    __syncthreads();
    if (rk[i] < KSEL) {
        int slot = 0;
        for (int j = 0; j < i; j++)
            if (rk[j] < KSEL) slot++;
        g_idx[slot] = i;
        if (has_lens) out[lens_off + slot] = (float)seq_lens[i];
    }
}

// ---------------------------------------------------------------------------
// K4: gather x_sel = x[idx][:, :max_time, :]
// ---------------------------------------------------------------------------
__global__ void gather_kernel(const float* __restrict__ x,
                              float* __restrict__ out, int max_time)
{
    const int s = blockIdx.y;
    long long n4 = (long long)max_time * (D_ / 4);
    long long i  = (long long)blockIdx.x * blockDim.x + threadIdx.x;
    if (i >= n4) return;
    int src_b = g_idx[s];
    const float4* src = (const float4*)(x + (size_t)src_b * T_ * D_);
    float4*       dst = (float4*)(out + (size_t)s * max_time * D_);
    dst[i] = src[i];
}

// ---------------------------------------------------------------------------
// Host launcher
// ---------------------------------------------------------------------------
extern "C" void kernel_launch(void* const* d_in, const int* in_sizes, int n_in,
                              void* d_out, int out_size)
{
    const float* x        = (const float*)d_in[0];
    const int*   seq_lens = (const int*)  d_in[1];
    const float* w1       = (const float*)d_in[2];
    const float* b1       = (const float*)d_in[3];
    const float* w2       = (const float*)d_in[4];
    const float* b2       = (const float*)d_in[5];
    float* out = (float*)d_out;

    const long long row_elems = (long long)KSEL * D_;
    int has_lens = ((long long)out_size % row_elems) != 0;
    long long mt = has_lens ? ((long long)out_size - KSEL) / row_elems
                            : (long long)out_size / row_elems;
    int max_time = (int)mt;

    cudaFuncSetAttribute(conv1_mma_kernel,
                         cudaFuncAttributeMaxDynamicSharedMemorySize, DYN_SMEM);

    prep_w_kernel<<<(NCH * KDIM + 255) / 256, 256>>>(w1);

    conv1_mma_kernel<<<NTILES, 256, DYN_SMEM>>>(x, b1);

    conv2_est_kernel<<<B_, 256>>>(w2, b2, seq_lens);

    select_kernel<<<1, B_>>>(seq_lens, out, (long long)KSEL * max_time * D_, has_lens);

    long long n4 = (long long)max_time * (D_ / 4);
    dim3 g4((unsigned)((n4 + 255) / 256), KSEL);
    gather_kernel<<<g4, 256>>>(x, out, max_time);
}